// round 1
// baseline (speedup 1.0000x reference)
#include <cuda_runtime.h>

#define C16  16
#define GH32 32
#define W512 512
#define HW   (512 * 512)

// Packed f32x2 FMA (Blackwell sm_103a). ptxas will not auto-fuse 2x fmaf;
// this is the only way to get FFMA2 (2 fp32 FMAs per instruction).
__device__ __forceinline__ float2 ffma2(float2 a, float2 b, float2 c) {
    float2 d;
    asm("fma.rn.f32x2 %0, %1, %2, %3;"
        : "=l"(reinterpret_cast<unsigned long long&>(d))
        : "l"(reinterpret_cast<unsigned long long&>(a)),
          "l"(reinterpret_cast<unsigned long long&>(b)),
          "l"(reinterpret_cast<unsigned long long&>(c)));
    return d;
}

// Fused kernel. Key identity: softmax over 8 identical affinities == 1/8 each,
// so agg = mean of 8 rolls of M = mw @ s + mb with s = mean of 8 rolls of x.
// hidden = relu(W1 @ x + W2 @ s + b1'), W2 = g1w[:,16:] @ mw (folded).
// out = agg * sigmoid(g2w @ hidden + g2b).
// One thread = 2 horizontally-adjacent pixels, all math in packed f32x2.
__global__ __launch_bounds__(128) void fused_graphaug_kernel(
    const float* __restrict__ x,
    const float* __restrict__ mw,  const float* __restrict__ mb,
    const float* __restrict__ g1w, const float* __restrict__ g1b,
    const float* __restrict__ g2w, const float* __restrict__ g2b,
    float* __restrict__ out)
{
    // Weights stored as duplicated pairs (w,w) so LDS.128 yields two
    // broadcast-ready f32x2 operands per load.
    __shared__ __align__(16) float smwT[C16 * C16 * 2];   // [c][d] = mw[d][c]
    __shared__ __align__(16) float sW1T[C16 * GH32 * 2];  // [c][j] = g1w[j][c]
    __shared__ __align__(16) float sW2T[C16 * GH32 * 2];  // [c][j] = (g1w[:,16:] @ mw)[j][c]
    __shared__ __align__(16) float sg2T[GH32 * C16 * 2];  // [j][g] = g2w[g][j]
    __shared__ __align__(16) float smbp[C16 * 2];
    __shared__ __align__(16) float sb1p[GH32 * 2];
    __shared__ __align__(16) float sgbp[C16 * 2];

    const int t = threadIdx.x;

    // ---- Stage weights (per block; tiny, L2-resident) ----
    for (int i = t; i < C16 * C16; i += 128) {
        int c = i >> 4, d = i & 15;
        float v = mw[d * C16 + c];
        smwT[i * 2] = v; smwT[i * 2 + 1] = v;
    }
    for (int i = t; i < C16 * GH32; i += 128) {
        int c = i >> 5, j = i & 31;
        float v = g1w[j * (2 * C16) + c];
        sW1T[i * 2] = v; sW1T[i * 2 + 1] = v;
        float acc = 0.f;
        #pragma unroll
        for (int k = 0; k < C16; k++)
            acc += g1w[j * (2 * C16) + C16 + k] * mw[k * C16 + c];
        sW2T[i * 2] = acc; sW2T[i * 2 + 1] = acc;
    }
    for (int i = t; i < GH32 * C16; i += 128) {
        int j = i >> 4, g = i & 15;
        float v = g2w[g * GH32 + j];
        sg2T[i * 2] = v; sg2T[i * 2 + 1] = v;
    }
    if (t < C16) {
        float v = mb[t];  smbp[2 * t] = v; smbp[2 * t + 1] = v;
        float u = g2b[t]; sgbp[2 * t] = u; sgbp[2 * t + 1] = u;
    }
    if (t < GH32) {
        float acc = g1b[t];
        #pragma unroll
        for (int k = 0; k < C16; k++)
            acc += g1w[t * (2 * C16) + C16 + k] * mb[k];
        sb1p[2 * t] = acc; sb1p[2 * t + 1] = acc;
    }
    __syncthreads();

    // ---- Pixel-pair indexing ----
    const int pair = blockIdx.x * 128 + t;          // 524288 pairs total
    const int p0   = pair * 2;                       // even pixel index
    const int w0   = p0 & (W512 - 1);
    const int h    = (p0 >> 9) & (W512 - 1);
    const int b    = p0 >> 18;

    const float* xb    = x + (size_t)b * C16 * HW;
    const int    center = h * W512 + w0;

    // Fixed offsets (dy,dx); source = ((h-dy)&511, (w-dx)&511)
    const int dy[8] = {-4, -4, -4, -3, -2, 2, 3, 4};
    const int dx[8] = {-4, -1,  2,  4, -3, 3, -2, 4};
    int off0[8], off1[8];
    #pragma unroll
    for (int i = 0; i < 8; i++) {
        int r  = (h - dy[i]) & (W512 - 1);
        int c0 = (w0     - dx[i]) & (W512 - 1);
        int c1 = (w0 + 1 - dx[i]) & (W512 - 1);
        off0[i] = r * W512 + c0;
        off1[i] = r * W512 + c1;
    }

    // ---- s = mean of 8 rolled x values, per channel (packed pair) ----
    float2 sv[C16];
    #pragma unroll
    for (int c = 0; c < C16; c++) {
        const float* xp = xb + c * HW;
        float a0 = 0.f, a1 = 0.f;
        #pragma unroll
        for (int i = 0; i < 8; i++) {
            a0 += __ldg(xp + off0[i]);
            a1 += __ldg(xp + off1[i]);
        }
        sv[c] = make_float2(a0 * 0.125f, a1 * 0.125f);
    }

    // ---- hidden (4 chunks of 8 units) feeding gate accumulators ----
    float2 gacc[C16];
    #pragma unroll
    for (int g = 0; g < C16; g++)
        gacc[g] = *reinterpret_cast<const float2*>(&sgbp[2 * g]);

    #pragma unroll
    for (int jt = 0; jt < 4; jt++) {
        const int jb = jt * 8;
        float2 hreg[8];
        #pragma unroll
        for (int jj = 0; jj < 8; jj++)
            hreg[jj] = *reinterpret_cast<const float2*>(&sb1p[2 * (jb + jj)]);

        // W1 @ x  (x re-loaded per chunk: L1-resident, saves 32 registers)
        #pragma unroll
        for (int c = 0; c < C16; c++) {
            float2 xc = *reinterpret_cast<const float2*>(xb + c * HW + center);
            #pragma unroll
            for (int jj = 0; jj < 8; jj += 2) {
                float4 wq = *reinterpret_cast<const float4*>(&sW1T[(c * GH32 + jb + jj) * 2]);
                hreg[jj]     = ffma2(make_float2(wq.x, wq.y), xc, hreg[jj]);
                hreg[jj + 1] = ffma2(make_float2(wq.z, wq.w), xc, hreg[jj + 1]);
            }
        }
        // W2 @ s
        #pragma unroll
        for (int c = 0; c < C16; c++) {
            float2 sc = sv[c];
            #pragma unroll
            for (int jj = 0; jj < 8; jj += 2) {
                float4 wq = *reinterpret_cast<const float4*>(&sW2T[(c * GH32 + jb + jj) * 2]);
                hreg[jj]     = ffma2(make_float2(wq.x, wq.y), sc, hreg[jj]);
                hreg[jj + 1] = ffma2(make_float2(wq.z, wq.w), sc, hreg[jj + 1]);
            }
        }
        // relu
        #pragma unroll
        for (int jj = 0; jj < 8; jj++) {
            hreg[jj].x = fmaxf(hreg[jj].x, 0.f);
            hreg[jj].y = fmaxf(hreg[jj].y, 0.f);
        }
        // gate pre-activation accumulation: gacc += g2w[:, j] * h_j
        #pragma unroll
        for (int jj = 0; jj < 8; jj++) {
            float2 hv = hreg[jj];
            const int j = jb + jj;
            #pragma unroll
            for (int g = 0; g < C16; g += 2) {
                float4 wq = *reinterpret_cast<const float4*>(&sg2T[(j * C16 + g) * 2]);
                gacc[g]     = ffma2(make_float2(wq.x, wq.y), hv, gacc[g]);
                gacc[g + 1] = ffma2(make_float2(wq.z, wq.w), hv, gacc[g + 1]);
            }
        }
    }

    // ---- agg = mw @ s + mb ----
    float2 agg[C16];
    #pragma unroll
    for (int d = 0; d < C16; d++)
        agg[d] = *reinterpret_cast<const float2*>(&smbp[2 * d]);
    #pragma unroll
    for (int c = 0; c < C16; c++) {
        float2 sc = sv[c];
        #pragma unroll
        for (int d = 0; d < C16; d += 2) {
            float4 wq = *reinterpret_cast<const float4*>(&smwT[(c * C16 + d) * 2]);
            agg[d]     = ffma2(make_float2(wq.x, wq.y), sc, agg[d]);
            agg[d + 1] = ffma2(make_float2(wq.z, wq.w), sc, agg[d + 1]);
        }
    }

    // ---- out = agg * sigmoid(gacc) ----
    float* ob = out + (size_t)b * C16 * HW + center;
    #pragma unroll
    for (int c = 0; c < C16; c++) {
        float gx = 1.f / (1.f + __expf(-gacc[c].x));
        float gy = 1.f / (1.f + __expf(-gacc[c].y));
        float2 o = make_float2(agg[c].x * gx, agg[c].y * gy);
        *reinterpret_cast<float2*>(ob + (size_t)c * HW) = o;
    }
}

extern "C" void kernel_launch(void* const* d_in, const int* in_sizes, int n_in,
                              void* d_out, int out_size) {
    // metadata order: x, qw, qb, kw, kb, mw, mb, scaling, g1w, g1b, g2w, g2b
    const float* x   = (const float*)d_in[0];
    const float* mw  = (const float*)d_in[5];
    const float* mb  = (const float*)d_in[6];
    const float* g1w = (const float*)d_in[8];
    const float* g1b = (const float*)d_in[9];
    const float* g2w = (const float*)d_in[10];
    const float* g2b = (const float*)d_in[11];
    float* out = (float*)d_out;

    // 4 * 512 * 512 pixels = 1,048,576 -> 524,288 pairs -> 4096 blocks x 128
    fused_graphaug_kernel<<<4096, 128>>>(x, mw, mb, g1w, g1b, g2w, g2b, out);
}

// round 2
// speedup vs baseline: 1.3852x; 1.3852x over previous
#include <cuda_runtime.h>

#define C16  16
#define GH32 32
#define W512 512
#define HW   (512 * 512)

// Packed f32x2 FMA (Blackwell sm_103a) — 2 fp32 FMAs per instruction.
__device__ __forceinline__ float2 ffma2(float2 a, float2 b, float2 c) {
    float2 d;
    asm("fma.rn.f32x2 %0, %1, %2, %3;"
        : "=l"(reinterpret_cast<unsigned long long&>(d))
        : "l"(reinterpret_cast<unsigned long long&>(a)),
          "l"(reinterpret_cast<unsigned long long&>(b)),
          "l"(reinterpret_cast<unsigned long long&>(c)));
    return d;
}

// Identity: softmax over 8 identical affinities = 1/8 each, so
//   s   = mean of 8 rolls of x
//   agg = mw @ s + mb
//   hidden = relu(W1 @ x + W2 @ s + b1'),  W2 = g1w[:,16:] @ mw (folded),
//            b1' = g1b + g1w[:,16:] @ mb
//   out = agg * sigmoid(g2w @ hidden + g2b)
//
// One thread = 2x2 pixel block (rows r0,r0+1; cols c0,c0+1), all math as
// two packed f32x2 lanes, so each weight LDS.128 feeds 4 FFMA2.
__global__ __launch_bounds__(256, 1) void fused_graphaug_kernel(
    const float* __restrict__ x,
    const float* __restrict__ mw,  const float* __restrict__ mb,
    const float* __restrict__ g1w, const float* __restrict__ g1b,
    const float* __restrict__ g2w, const float* __restrict__ g2b,
    float* __restrict__ out)
{
    // Weights as duplicated pairs (w,w): LDS.128 -> two broadcast f32x2 operands.
    __shared__ __align__(16) float smwD[C16 * C16 * 2];   // [d][c] = mw[d][c]  (agg streaming)
    __shared__ __align__(16) float sW1T[C16 * GH32 * 2];  // [c][j] = g1w[j][c]
    __shared__ __align__(16) float sW2T[C16 * GH32 * 2];  // [c][j] = (g1w[:,16:] @ mw)[j][c]
    __shared__ __align__(16) float sg2T[GH32 * C16 * 2];  // [j][g] = g2w[g][j]
    __shared__ __align__(16) float smbp[C16 * 2];
    __shared__ __align__(16) float sb1p[GH32 * 2];
    __shared__ __align__(16) float sgbp[C16 * 2];

    const int t = threadIdx.x;

    // ---- Stage weights ----
    for (int i = t; i < C16 * C16; i += 256) {
        int d = i >> 4, c = i & 15;
        float v = mw[d * C16 + c];               // [d][c] layout for agg streaming
        smwD[i * 2] = v; smwD[i * 2 + 1] = v;
    }
    for (int i = t; i < C16 * GH32; i += 256) {
        int c = i >> 5, j = i & 31;
        float v = g1w[j * (2 * C16) + c];
        sW1T[i * 2] = v; sW1T[i * 2 + 1] = v;
        float acc = 0.f;
        #pragma unroll
        for (int k = 0; k < C16; k++)
            acc += g1w[j * (2 * C16) + C16 + k] * mw[k * C16 + c];
        sW2T[i * 2] = acc; sW2T[i * 2 + 1] = acc;
    }
    for (int i = t; i < GH32 * C16; i += 256) {
        int j = i >> 4, g = i & 15;
        float v = g2w[g * GH32 + j];
        sg2T[i * 2] = v; sg2T[i * 2 + 1] = v;
    }
    if (t < C16) {
        float v = mb[t];  smbp[2 * t] = v; smbp[2 * t + 1] = v;
        float u = g2b[t]; sgbp[2 * t] = u; sgbp[2 * t + 1] = u;
    }
    if (t >= 32 && t < 32 + GH32) {
        int j = t - 32;
        float acc = g1b[j];
        #pragma unroll
        for (int k = 0; k < C16; k++)
            acc += g1w[j * (2 * C16) + C16 + k] * mb[k];
        sb1p[2 * j] = acc; sb1p[2 * j + 1] = acc;
    }
    __syncthreads();

    // ---- 2x2 pixel-block indexing ----
    // 1024 blocks: b = blk>>8, row-pair rb = blk&255. 256 threads: col pair c0 = 2t.
    const int b  = blockIdx.x >> 8;
    const int rb = blockIdx.x & 255;
    const int r0 = rb * 2;
    const int r1 = r0 + 1;
    const int c0 = t * 2;

    const float* xb  = x + (size_t)b * C16 * HW;
    const int cen0 = r0 * W512 + c0;
    const int cen1 = r1 * W512 + c0;

    // Fixed offsets (dy,dx); source = ((r-dy)&511, (c-dx)&511)
    constexpr int DY[8] = {-4, -4, -4, -3, -2, 2, 3, 4};
    constexpr int DX[8] = {-4, -1,  2,  4, -3, 3, -2, 4};
    int ro0[8], ro1[8], cb[8], cb2[8];
    #pragma unroll
    for (int i = 0; i < 8; i++) {
        ro0[i] = ((r0 - DY[i]) & (W512 - 1)) * W512;
        ro1[i] = ((r1 - DY[i]) & (W512 - 1)) * W512;
        cb[i]  = (c0 - DX[i]) & (W512 - 1);
        cb2[i] = (cb[i] + 1) & (W512 - 1);
    }

    // ---- s = mean of 8 rolls, per channel; two f32x2 lanes (row0, row1) ----
    float2 sv0[C16], sv1[C16];
    #pragma unroll
    for (int c = 0; c < C16; c++) {
        const float* xp = xb + c * HW;
        float2 a0 = make_float2(0.f, 0.f), a1 = make_float2(0.f, 0.f);
        #pragma unroll
        for (int i = 0; i < 8; i++) {
            if ((DX[i] & 1) == 0) {
                // even dx: cb even, <= 510 -> aligned contiguous float2
                float2 v0 = *reinterpret_cast<const float2*>(xp + ro0[i] + cb[i]);
                float2 v1 = *reinterpret_cast<const float2*>(xp + ro1[i] + cb[i]);
                a0.x += v0.x; a0.y += v0.y;
                a1.x += v1.x; a1.y += v1.y;
            } else {
                a0.x += __ldg(xp + ro0[i] + cb[i]);  a0.y += __ldg(xp + ro0[i] + cb2[i]);
                a1.x += __ldg(xp + ro1[i] + cb[i]);  a1.y += __ldg(xp + ro1[i] + cb2[i]);
            }
        }
        sv0[c] = make_float2(a0.x * 0.125f, a0.y * 0.125f);
        sv1[c] = make_float2(a1.x * 0.125f, a1.y * 0.125f);
    }

    // ---- gate accumulators ----
    float2 gacc0[C16], gacc1[C16];
    #pragma unroll
    for (int g = 0; g < C16; g++) {
        float2 gb = *reinterpret_cast<const float2*>(&sgbp[2 * g]);
        gacc0[g] = gb; gacc1[g] = gb;
    }

    // ---- hidden in 4 chunks of 8 units ----
    #pragma unroll
    for (int jt = 0; jt < 4; jt++) {
        const int jb = jt * 8;
        float2 h0[8], h1[8];
        #pragma unroll
        for (int jj = 0; jj < 8; jj++) {
            float2 bv = *reinterpret_cast<const float2*>(&sb1p[2 * (jb + jj)]);
            h0[jj] = bv; h1[jj] = bv;
        }
        // W1 @ x (x re-loaded per chunk: L1-resident)
        #pragma unroll
        for (int c = 0; c < C16; c++) {
            float2 x0 = *reinterpret_cast<const float2*>(xb + c * HW + cen0);
            float2 x1 = *reinterpret_cast<const float2*>(xb + c * HW + cen1);
            #pragma unroll
            for (int jj = 0; jj < 8; jj += 2) {
                float4 wq = *reinterpret_cast<const float4*>(&sW1T[(c * GH32 + jb + jj) * 2]);
                float2 wa = make_float2(wq.x, wq.y), wb = make_float2(wq.z, wq.w);
                h0[jj]     = ffma2(wa, x0, h0[jj]);
                h1[jj]     = ffma2(wa, x1, h1[jj]);
                h0[jj + 1] = ffma2(wb, x0, h0[jj + 1]);
                h1[jj + 1] = ffma2(wb, x1, h1[jj + 1]);
            }
        }
        // W2 @ s
        #pragma unroll
        for (int c = 0; c < C16; c++) {
            float2 s0 = sv0[c], s1 = sv1[c];
            #pragma unroll
            for (int jj = 0; jj < 8; jj += 2) {
                float4 wq = *reinterpret_cast<const float4*>(&sW2T[(c * GH32 + jb + jj) * 2]);
                float2 wa = make_float2(wq.x, wq.y), wb = make_float2(wq.z, wq.w);
                h0[jj]     = ffma2(wa, s0, h0[jj]);
                h1[jj]     = ffma2(wa, s1, h1[jj]);
                h0[jj + 1] = ffma2(wb, s0, h0[jj + 1]);
                h1[jj + 1] = ffma2(wb, s1, h1[jj + 1]);
            }
        }
        // relu
        #pragma unroll
        for (int jj = 0; jj < 8; jj++) {
            h0[jj].x = fmaxf(h0[jj].x, 0.f); h0[jj].y = fmaxf(h0[jj].y, 0.f);
            h1[jj].x = fmaxf(h1[jj].x, 0.f); h1[jj].y = fmaxf(h1[jj].y, 0.f);
        }
        // gate pre-activation: gacc += g2w[:, j] * h_j
        #pragma unroll
        for (int jj = 0; jj < 8; jj++) {
            float2 hv0 = h0[jj], hv1 = h1[jj];
            const int j = jb + jj;
            #pragma unroll
            for (int g = 0; g < C16; g += 2) {
                float4 wq = *reinterpret_cast<const float4*>(&sg2T[(j * C16 + g) * 2]);
                float2 wa = make_float2(wq.x, wq.y), wb = make_float2(wq.z, wq.w);
                gacc0[g]     = ffma2(wa, hv0, gacc0[g]);
                gacc1[g]     = ffma2(wa, hv1, gacc1[g]);
                gacc0[g + 1] = ffma2(wb, hv0, gacc0[g + 1]);
                gacc1[g + 1] = ffma2(wb, hv1, gacc1[g + 1]);
            }
        }
    }

    // ---- stream agg per output channel, gate + store (keeps regs low) ----
    float* ob = out + (size_t)b * C16 * HW;
    #pragma unroll
    for (int d = 0; d < C16; d++) {
        float2 mbv = *reinterpret_cast<const float2*>(&smbp[2 * d]);
        float2 ag0 = mbv, ag1 = mbv;
        #pragma unroll
        for (int c = 0; c < C16; c += 2) {
            float4 wq = *reinterpret_cast<const float4*>(&smwD[(d * C16 + c) * 2]);
            float2 wa = make_float2(wq.x, wq.y), wb = make_float2(wq.z, wq.w);
            ag0 = ffma2(wa, sv0[c],     ag0);
            ag1 = ffma2(wa, sv1[c],     ag1);
            ag0 = ffma2(wb, sv0[c + 1], ag0);
            ag1 = ffma2(wb, sv1[c + 1], ag1);
        }
        float g00 = 1.f / (1.f + __expf(-gacc0[d].x));
        float g01 = 1.f / (1.f + __expf(-gacc0[d].y));
        float g10 = 1.f / (1.f + __expf(-gacc1[d].x));
        float g11 = 1.f / (1.f + __expf(-gacc1[d].y));
        float2 o0 = make_float2(ag0.x * g00, ag0.y * g01);
        float2 o1 = make_float2(ag1.x * g10, ag1.y * g11);
        *reinterpret_cast<float2*>(ob + (size_t)d * HW + cen0) = o0;
        *reinterpret_cast<float2*>(ob + (size_t)d * HW + cen1) = o1;
    }
}

extern "C" void kernel_launch(void* const* d_in, const int* in_sizes, int n_in,
                              void* d_out, int out_size) {
    // metadata order: x, qw, qb, kw, kb, mw, mb, scaling, g1w, g1b, g2w, g2b
    const float* x   = (const float*)d_in[0];
    const float* mw  = (const float*)d_in[5];
    const float* mb  = (const float*)d_in[6];
    const float* g1w = (const float*)d_in[8];
    const float* g1b = (const float*)d_in[9];
    const float* g2w = (const float*)d_in[10];
    const float* g2b = (const float*)d_in[11];
    float* out = (float*)d_out;

    // 4 batches x 256 row-pairs = 1024 blocks; 256 threads x (2x2 px) = 1024 px/block
    fused_graphaug_kernel<<<1024, 256>>>(x, mw, mb, g1w, g1b, g2w, g2b, out);
}